// round 13
// baseline (speedup 1.0000x reference)
#include <cuda_runtime.h>
#include <cstdint>

// EdgeModel: out[e,:] = relu([src,dest,attr,u[batch]] @ W1 + b1) @ W2 + b2
// E = 8e6, B = 4096, W1:(4,10), W2:(10,19). Output [E,19] f32.
//
// R12: persistent CTAs + double-buffered tile pipeline.
// Diagnosis: dur pinned ~175us across occ 30-47% / issue 34-51% / L1 43-68%
// -> fixed ~5us per-CTA serial latency (barrier -> TMA store -> wait_group 0
// drain -> CTA relaunch), paid by all 15625 CTAs.
// Fix: each CTA grid-strides over 256-edge tiles with TWO smem buffers;
// tile i's TMA store drains while tile i+1 is computed (wait_group 1 gates
// buffer reuse). Final drain paid once per CTA (608 CTAs, not 15625).
// Compute codegen = R8 shape (best known): const-bank weight pack, packed
// f32x2 math, carry-paired conflict-free float2 tile stores.

#define TPB 128
#define EDGES_PER_TILE 256        // TPB * 2
#define TILE_BYTES 19456          // 256 * 19 * 4
#define GRID_CTAS 608             // ~4 per SM, grid-stride

typedef unsigned long long u64;

__device__ int g_batch_is64;   // 1 if batch is int64, 0 if int32

struct CWPack {
    u64 w1p[40];    // {W1[c][k]}x2, index c*10+k
    u64 b1p[10];    // {b1[k]}x2
    u64 w2p[190];   // {W2[k][j]}x2 transposed, index j*10+k  (16B-aligned rows)
    u64 b2p[19];    // {b2[j]}x2
    u64 pad;
};

__device__ CWPack g_wscratch;      // staging (written by prep kernel)
__constant__ CWPack c_w;           // read-only broadcast copy

__device__ __forceinline__ u64 pack2(float lo, float hi) {
    u64 r;
    asm("mov.b64 %0, {%1, %2};" : "=l"(r) : "f"(lo), "f"(hi));
    return r;
}

__device__ __forceinline__ void unpack2(u64 v, float& lo, float& hi) {
    asm("mov.b64 {%0, %1}, %2;" : "=f"(lo), "=f"(hi) : "l"(v));
}

__device__ __forceinline__ u64 fma2(u64 a, u64 b, u64 c) {
    u64 d;
    asm("fma.rn.f32x2 %0, %1, %2, %3;" : "=l"(d) : "l"(a), "l"(b), "l"(c));
    return d;
}

__device__ __forceinline__ u64 relu2(u64 v) {
    float lo, hi;
    unpack2(v, lo, hi);
    lo = fmaxf(lo, 0.0f);
    hi = fmaxf(hi, 0.0f);
    return pack2(lo, hi);
}

// Build weight pack + detect batch dtype (int64 values 0..4095 -> all odd
// int32 words zero; 1024 random int32 in [0,4096) all-zero: impossible).
__global__ void prep_weights(const float* __restrict__ W1,
                             const float* __restrict__ b1,
                             const float* __restrict__ W2,
                             const float* __restrict__ b2,
                             const int*   __restrict__ b32)
{
    int t = threadIdx.x;
    if (t < 40)             g_wscratch.w1p[t]      = pack2(W1[t], W1[t]);
    if (t >= 64 && t < 74)  g_wscratch.b1p[t - 64] = pack2(b1[t - 64], b1[t - 64]);
    if (t >= 96 && t < 115) g_wscratch.b2p[t - 96] = pack2(b2[t - 96], b2[t - 96]);
    if (t < 190) {
        int j = t / 10, k = t - j * 10;   // transpose
        float w = W2[k * 19 + j];
        g_wscratch.w2p[t] = pack2(w, w);
    }
    if (t == 255) g_wscratch.pad = 0;

    if (t >= 192 && t < 224) {            // warp 6: parallel dtype scan
        int lane = t - 192;
        int bad = 0;
        #pragma unroll 4
        for (int i = 0; i < 32; i++)
            bad |= b32[1 + 2 * (lane * 32 + i)];
        unsigned any = __ballot_sync(0xffffffffu, bad != 0);
        if (lane == 0) g_batch_is64 = (any == 0) ? 1 : 0;
    }
}

__global__ __launch_bounds__(TPB, 4)
void edge_model_kernel(const float* __restrict__ src,
                       const float* __restrict__ dest,
                       const float* __restrict__ ea,
                       const float* __restrict__ u,
                       const void*  __restrict__ batch_raw,
                       float* __restrict__ out,        // [E,19]
                       long long E)
{
    // Two tile buffers, contiguous: buf b at otile + b*4864 floats.
    __shared__ __align__(16) float otile[2 * EDGES_PER_TILE * 19];  // 38912 B

    const int t = threadIdx.x;
    const int is64 = g_batch_is64;
    const int n_tiles = (int)(E / EDGES_PER_TILE);   // full tiles

    int it = 0;   // local iteration counter (buffer parity + wait warmup)
    for (int tile = blockIdx.x; tile < n_tiles; tile += gridDim.x, it++) {
        const int buf = it & 1;

        // Gate buffer reuse: allow at most 1 outstanding bulk-store group,
        // so the store of tile (it-2) — same buffer — has completed.
        if (it >= 2 && t == 0)
            asm volatile("cp.async.bulk.wait_group 1;" ::: "memory");
        __syncthreads();   // buffer writable by all warps

        // ---------------- compute 256 edges (2 per thread) ----------------
        const unsigned p = (unsigned)tile * (EDGES_PER_TILE / 2) + (unsigned)t;

        const float2 s = ((const float2*)src)[p];
        const float2 d = ((const float2*)dest)[p];
        const float2 a = ((const float2*)ea)[p];

        int i0, i1;
        if (is64) {
            longlong2 bi = ((const longlong2*)batch_raw)[p];
            i0 = (int)bi.x; i1 = (int)bi.y;
        } else {
            int2 bi = ((const int2*)batch_raw)[p];
            i0 = bi.x; i1 = bi.y;
        }
        const float u0 = __ldg(&u[i0]);
        const float u1 = __ldg(&u[i1]);

        const u64 sp = pack2(s.x, s.y);
        const u64 dp = pack2(d.x, d.y);
        const u64 ap = pack2(a.x, a.y);
        const u64 up = pack2(u0, u1);

        // layer 1 (weights from constant bank)
        u64 h[10];
        #pragma unroll
        for (int k = 0; k < 10; k++) {
            u64 acc = c_w.b1p[k];
            acc = fma2(sp, c_w.w1p[k],      acc);
            acc = fma2(dp, c_w.w1p[10 + k], acc);
            acc = fma2(ap, c_w.w1p[20 + k], acc);
            acc = fma2(up, c_w.w1p[30 + k], acc);
            h[k] = relu2(acc);
        }

        // layer 2 into smem tile (R8 carry-paired conflict-free stores)
        float* row0 = &otile[buf * (EDGES_PER_TILE * 19) + (2 * t)     * 19];
        float* row1 = &otile[buf * (EDGES_PER_TILE * 19) + (2 * t + 1) * 19];

        u64 prev;
        {   // j = 0
            u64 acc = c_w.b2p[0];
            const ulonglong2* wr = (const ulonglong2*)&c_w.w2p[0];
            #pragma unroll
            for (int kk = 0; kk < 5; kk++) {
                ulonglong2 w = wr[kk];
                acc = fma2(h[2 * kk],     w.x, acc);
                acc = fma2(h[2 * kk + 1], w.y, acc);
            }
            float lo, hi;
            unpack2(acc, lo, hi);
            row1[0] = hi;              // scalar leftover
            prev = acc;
        }
        #pragma unroll 2
        for (int j = 1; j < 19; j++) {
            u64 acc = c_w.b2p[j];
            const ulonglong2* wr = (const ulonglong2*)&c_w.w2p[j * 10];
            #pragma unroll
            for (int kk = 0; kk < 5; kk++) {
                ulonglong2 w = wr[kk];
                acc = fma2(h[2 * kk],     w.x, acc);
                acc = fma2(h[2 * kk + 1], w.y, acc);
            }
            float pl, ph, cl, ch;
            unpack2(prev, pl, ph);
            unpack2(acc,  cl, ch);
            if (j & 1) *(float2*)(row0 + j - 1) = make_float2(pl, cl);
            else       *(float2*)(row1 + j - 1) = make_float2(ph, ch);
            prev = acc;
        }
        {   // tail: row0[18]
            float lo, hi;
            unpack2(prev, lo, hi);
            row0[18] = lo;             // scalar leftover
        }
        __syncthreads();   // tile fully written

        // Issue the bulk store; do NOT wait here (drain overlaps next tile).
        if (t == 0) {
            float* wtile = &otile[buf * (EDGES_PER_TILE * 19)];
            unsigned saddr = (unsigned)__cvta_generic_to_shared(wtile);
            const float* g = out + (long long)tile * (EDGES_PER_TILE * 19);
            asm volatile("fence.proxy.async.shared::cta;" ::: "memory");
            asm volatile(
                "cp.async.bulk.global.shared::cta.bulk_group [%0], [%1], %2;"
                :: "l"(g), "r"(saddr), "r"((unsigned)TILE_BYTES) : "memory");
            asm volatile("cp.async.bulk.commit_group;" ::: "memory");
        }
    }

    // Drain all outstanding stores once per CTA.
    if (t == 0)
        asm volatile("cp.async.bulk.wait_group 0;" ::: "memory");

    // ---- tail edges (E not multiple of 256), scalar, grid-stride ----
    const long long tail_start = (long long)n_tiles * EDGES_PER_TILE;
    for (long long e = tail_start + (long long)blockIdx.x * TPB + t;
         e < E; e += (long long)gridDim.x * TPB) {
        float x0 = src[e], x1 = dest[e], x2 = ea[e];
        long long bi = is64 ? ((const long long*)batch_raw)[e]
                            : (long long)((const int*)batch_raw)[e];
        float x3 = u[bi];
        float h[10];
        #pragma unroll
        for (int k = 0; k < 10; k++) {
            float lo, hiu;
            unpack2(c_w.w1p[k], lo, hiu);       float wa = lo;
            unpack2(c_w.w1p[10 + k], lo, hiu);  float wb = lo;
            unpack2(c_w.w1p[20 + k], lo, hiu);  float wc = lo;
            unpack2(c_w.w1p[30 + k], lo, hiu);  float wd = lo;
            unpack2(c_w.b1p[k], lo, hiu);
            float acc = lo;
            acc = fmaf(x0, wa, acc);
            acc = fmaf(x1, wb, acc);
            acc = fmaf(x2, wc, acc);
            acc = fmaf(x3, wd, acc);
            h[k] = fmaxf(acc, 0.0f);
        }
        #pragma unroll
        for (int j = 0; j < 19; j++) {
            float lo, hiu;
            unpack2(c_w.b2p[j], lo, hiu);
            float acc = lo;
            #pragma unroll
            for (int k = 0; k < 10; k++) {
                unpack2(c_w.w2p[j * 10 + k], lo, hiu);
                acc = fmaf(h[k], lo, acc);
            }
            out[e * 19 + j] = acc;
        }
    }
}

extern "C" void kernel_launch(void* const* d_in, const int* in_sizes, int n_in,
                              void* d_out, int out_size)
{
    const float* src   = (const float*)d_in[0];
    const float* dest  = (const float*)d_in[1];
    const float* ea    = (const float*)d_in[2];
    const float* u     = (const float*)d_in[3];
    const void*  batch = d_in[4];
    const float* W1    = (const float*)d_in[5];
    const float* b1    = (const float*)d_in[6];
    const float* W2    = (const float*)d_in[7];
    const float* b2    = (const float*)d_in[8];
    float* out = (float*)d_out;

    const long long E = in_sizes[0];
    const int n_tiles = (int)(E / EDGES_PER_TILE);
    int blocks = GRID_CTAS;
    if (blocks > n_tiles && n_tiles > 0) blocks = n_tiles;
    if (n_tiles == 0) blocks = 1;

    prep_weights<<<1, 256>>>(W1, b1, W2, b2, (const int*)batch);

    void* scratch_addr = nullptr;
    cudaGetSymbolAddress(&scratch_addr, g_wscratch);
    cudaMemcpyToSymbolAsync(c_w, scratch_addr, sizeof(CWPack), 0,
                            cudaMemcpyDeviceToDevice, 0);

    edge_model_kernel<<<blocks, TPB>>>(src, dest, ea, u, batch, out, E);
}

// round 14
// speedup vs baseline: 1.1340x; 1.1340x over previous
#include <cuda_runtime.h>
#include <cstdint>

// EdgeModel: out[e,:] = relu([src,dest,attr,u[batch]] @ W1 + b1) @ W2 + b2
// E = 8e6, B = 4096, W1:(4,10), W2:(10,19). Output [E,19] f32.
//
// R13 = R8 (best, 178.7us) + minimal deltas:
//  - per-warp TMA bulk stores (each warp flushes its own contiguous 64x19
//    slice after __syncwarp) -> no block-barrier convoy, parallel store
//    issue. Keeps R8's (256,3) 80-reg unroll-2 codegen exactly.
//  - batch index load issued first (heads the dependent batch->u chain).
// Model: kernel is near the effective HBM ceiling (~3.9-4.2TB/s for this
// 80%-write mix); these deltas recover barrier/issue slack, not structure.

#define TPB 256
#define EDGES_PER_BLOCK 512   // TPB * 2
#define WARP_TILE_BYTES 4864  // 64 edges * 19 * 4

typedef unsigned long long u64;

__device__ int g_batch_is64;   // 1 if batch is int64, 0 if int32

struct CWPack {
    u64 w1p[40];    // {W1[c][k]}x2, index c*10+k
    u64 b1p[10];    // {b1[k]}x2
    u64 w2p[190];   // {W2[k][j]}x2 transposed, index j*10+k  (16B-aligned rows)
    u64 b2p[19];    // {b2[j]}x2
    u64 pad;
};

__device__ CWPack g_wscratch;      // staging (written by prep kernel)
__constant__ CWPack c_w;           // read-only broadcast copy

__device__ __forceinline__ u64 pack2(float lo, float hi) {
    u64 r;
    asm("mov.b64 %0, {%1, %2};" : "=l"(r) : "f"(lo), "f"(hi));
    return r;
}

__device__ __forceinline__ void unpack2(u64 v, float& lo, float& hi) {
    asm("mov.b64 {%0, %1}, %2;" : "=f"(lo), "=f"(hi) : "l"(v));
}

__device__ __forceinline__ u64 fma2(u64 a, u64 b, u64 c) {
    u64 d;
    asm("fma.rn.f32x2 %0, %1, %2, %3;" : "=l"(d) : "l"(a), "l"(b), "l"(c));
    return d;
}

__device__ __forceinline__ u64 relu2(u64 v) {
    float lo, hi;
    unpack2(v, lo, hi);
    lo = fmaxf(lo, 0.0f);
    hi = fmaxf(hi, 0.0f);
    return pack2(lo, hi);
}

// Build weight pack + detect batch dtype (int64 values 0..4095 -> all odd
// int32 words zero; 1024 random int32 in [0,4096) all-zero: impossible).
__global__ void prep_weights(const float* __restrict__ W1,
                             const float* __restrict__ b1,
                             const float* __restrict__ W2,
                             const float* __restrict__ b2,
                             const int*   __restrict__ b32)
{
    int t = threadIdx.x;
    if (t < 40)             g_wscratch.w1p[t]      = pack2(W1[t], W1[t]);
    if (t >= 64 && t < 74)  g_wscratch.b1p[t - 64] = pack2(b1[t - 64], b1[t - 64]);
    if (t >= 96 && t < 115) g_wscratch.b2p[t - 96] = pack2(b2[t - 96], b2[t - 96]);
    if (t < 190) {
        int j = t / 10, k = t - j * 10;   // transpose
        float w = W2[k * 19 + j];
        g_wscratch.w2p[t] = pack2(w, w);
    }
    if (t == 255) g_wscratch.pad = 0;

    if (t >= 192 && t < 224) {            // warp 6: parallel dtype scan
        int lane = t - 192;
        int bad = 0;
        #pragma unroll 4
        for (int i = 0; i < 32; i++)
            bad |= b32[1 + 2 * (lane * 32 + i)];
        unsigned any = __ballot_sync(0xffffffffu, bad != 0);
        if (lane == 0) g_batch_is64 = (any == 0) ? 1 : 0;
    }
}

__global__ __launch_bounds__(TPB, 3)
void edge_model_kernel(const float* __restrict__ src,
                       const float* __restrict__ dest,
                       const float* __restrict__ ea,
                       const float* __restrict__ u,
                       const void*  __restrict__ batch_raw,
                       float* __restrict__ out,        // [E,19]
                       long long E)
{
    __shared__ __align__(16) float otile[EDGES_PER_BLOCK * 19];  // 38912 B

    const int t = threadIdx.x;
    const int is64 = g_batch_is64;

    const long long base = (long long)blockIdx.x * EDGES_PER_BLOCK;

    if (base + EDGES_PER_BLOCK <= E) {
        // ============== fast path: full 512-edge block, 2 edges/thread ==============
        const long long p = (base >> 1) + t;   // pair index

        // Batch indices FIRST: they head the only dependent chain (batch -> u).
        long long i0, i1;
        if (is64) {
            longlong2 bi = ((const longlong2*)batch_raw)[p];
            i0 = bi.x; i1 = bi.y;
        } else {
            int2 bi = ((const int2*)batch_raw)[p];
            i0 = bi.x; i1 = bi.y;
        }
        const float u0 = __ldg(&u[i0]);
        const float u1 = __ldg(&u[i1]);

        const float2 s = ((const float2*)src)[p];
        const float2 d = ((const float2*)dest)[p];
        const float2 a = ((const float2*)ea)[p];

        const u64 sp = pack2(s.x, s.y);
        const u64 dp = pack2(d.x, d.y);
        const u64 ap = pack2(a.x, a.y);
        const u64 up = pack2(u0, u1);

        // layer 1 (weights from constant bank — no L1 traffic)
        u64 h[10];
        #pragma unroll
        for (int k = 0; k < 10; k++) {
            u64 acc = c_w.b1p[k];
            acc = fma2(sp, c_w.w1p[k],      acc);
            acc = fma2(dp, c_w.w1p[10 + k], acc);
            acc = fma2(ap, c_w.w1p[20 + k], acc);
            acc = fma2(up, c_w.w1p[30 + k], acc);
            h[k] = relu2(acc);
        }

        // layer 2 into smem tile. Accs hold {edge0_j, edge1_j}; a 1-element
        // carry re-pairs them into (j-1, j) float2 stores per edge row:
        //   j odd : row0 pair at word 38t + (j-1)      (even -> 8B aligned)
        //   j even: row1 pair at word 38t + 19 + (j-1) (even -> 8B aligned)
        // u64 lane stride = 19 (odd) -> conflict-free.
        float* row0 = &otile[(2 * t)     * 19];
        float* row1 = &otile[(2 * t + 1) * 19];

        u64 prev;
        {   // j = 0
            u64 acc = c_w.b2p[0];
            const ulonglong2* wr = (const ulonglong2*)&c_w.w2p[0];
            #pragma unroll
            for (int kk = 0; kk < 5; kk++) {
                ulonglong2 w = wr[kk];
                acc = fma2(h[2 * kk],     w.x, acc);
                acc = fma2(h[2 * kk + 1], w.y, acc);
            }
            float lo, hi;
            unpack2(acc, lo, hi);
            row1[0] = hi;              // scalar leftover (1 instr)
            prev = acc;
        }
        #pragma unroll 2
        for (int j = 1; j < 19; j++) {
            u64 acc = c_w.b2p[j];
            const ulonglong2* wr = (const ulonglong2*)&c_w.w2p[j * 10];  // 16B aligned
            #pragma unroll
            for (int kk = 0; kk < 5; kk++) {
                ulonglong2 w = wr[kk];
                acc = fma2(h[2 * kk],     w.x, acc);
                acc = fma2(h[2 * kk + 1], w.y, acc);
            }
            float pl, ph, cl, ch;
            unpack2(prev, pl, ph);
            unpack2(acc,  cl, ch);
            if (j & 1) *(float2*)(row0 + j - 1) = make_float2(pl, cl);
            else       *(float2*)(row1 + j - 1) = make_float2(ph, ch);
            prev = acc;
        }
        {   // tail: row0[18]
            float lo, hi;
            unpack2(prev, lo, hi);
            row0[18] = lo;             // scalar leftover (1 instr)
        }

        // Per-warp TMA bulk store: warp w owns rows [64w, 64w+64) — written
        // only by its own threads, so __syncwarp suffices. No block barrier.
        __syncwarp();
        asm volatile("fence.proxy.async.shared::cta;" ::: "memory");
        if ((t & 31) == 0) {
            const int w = t >> 5;                       // warp id
            float* wtile = &otile[(64 * w) * 19];
            unsigned saddr = (unsigned)__cvta_generic_to_shared(wtile);
            const float* g = out + (base + 64 * w) * 19;   // 16B-aligned
            asm volatile(
                "cp.async.bulk.global.shared::cta.bulk_group [%0], [%1], %2;"
                :: "l"(g), "r"(saddr), "r"((unsigned)WARP_TILE_BYTES) : "memory");
            asm volatile("cp.async.bulk.commit_group;" ::: "memory");
            asm volatile("cp.async.bulk.wait_group 0;" ::: "memory");
        }
    } else {
        // ================= tail path (scalar, bounds-checked) =================
        for (long long e = base + t; e < E; e += TPB) {
            float x0 = src[e], x1 = dest[e], x2 = ea[e];
            long long bi = is64 ? ((const long long*)batch_raw)[e]
                                : (long long)((const int*)batch_raw)[e];
            float x3 = u[bi];
            float h[10];
            #pragma unroll
            for (int k = 0; k < 10; k++) {
                float lo, hiu;
                unpack2(c_w.w1p[k], lo, hiu);       float wa = lo;
                unpack2(c_w.w1p[10 + k], lo, hiu);  float wb = lo;
                unpack2(c_w.w1p[20 + k], lo, hiu);  float wc = lo;
                unpack2(c_w.w1p[30 + k], lo, hiu);  float wd = lo;
                unpack2(c_w.b1p[k], lo, hiu);
                float acc = lo;
                acc = fmaf(x0, wa, acc);
                acc = fmaf(x1, wb, acc);
                acc = fmaf(x2, wc, acc);
                acc = fmaf(x3, wd, acc);
                h[k] = fmaxf(acc, 0.0f);
            }
            #pragma unroll
            for (int j = 0; j < 19; j++) {
                float lo, hiu;
                unpack2(c_w.b2p[j], lo, hiu);
                float acc = lo;
                #pragma unroll
                for (int k = 0; k < 10; k++) {
                    unpack2(c_w.w2p[j * 10 + k], lo, hiu);
                    acc = fmaf(h[k], lo, acc);
                }
                out[e * 19 + j] = acc;
            }
        }
    }
}

extern "C" void kernel_launch(void* const* d_in, const int* in_sizes, int n_in,
                              void* d_out, int out_size)
{
    const float* src   = (const float*)d_in[0];
    const float* dest  = (const float*)d_in[1];
    const float* ea    = (const float*)d_in[2];
    const float* u     = (const float*)d_in[3];
    const void*  batch = d_in[4];
    const float* W1    = (const float*)d_in[5];
    const float* b1    = (const float*)d_in[6];
    const float* W2    = (const float*)d_in[7];
    const float* b2    = (const float*)d_in[8];
    float* out = (float*)d_out;

    const long long E = in_sizes[0];
    const int blocks = (int)((E + EDGES_PER_BLOCK - 1) / EDGES_PER_BLOCK);

    prep_weights<<<1, 256>>>(W1, b1, W2, b2, (const int*)batch);

    void* scratch_addr = nullptr;
    cudaGetSymbolAddress(&scratch_addr, g_wscratch);
    cudaMemcpyToSymbolAsync(c_w, scratch_addr, sizeof(CWPack), 0,
                            cudaMemcpyDeviceToDevice, 0);

    edge_model_kernel<<<blocks, TPB>>>(src, dest, ea, u, batch, out, E);
}

// round 15
// speedup vs baseline: 1.4909x; 1.3147x over previous
#include <cuda_runtime.h>
#include <cstdint>

// EdgeModel: out[e,:] = relu([src,dest,attr,u[batch]] @ W1 + b1) @ W2 + b2
// E = 8e6, B = 4096, W1:(4,10), W2:(10,19). Output [E,19] f32.
//
// R14: amortize the const-port weight loads (the real plateau).
// Model: GPR-dest LDC has an 8-cyc/SMSP structural floor; R8 pays ~164 LDC
// per 2 edges -> ~154us of pure const-port time = the 174-178us wall seen by
// five structurally different kernels (R11 moved it to the L1 port, same
// wall). Fix: 4 edges/thread (two packed pairs share every LDC) -> const
// port ~77us, below the ~110-130us DRAM stream.
// Shape: TPB=128, 512-edge tile (38.9KB, unchanged), single block TMA bulk
// store (R8's best store path), __launch_bounds__(128,5) -> 20 warps/SM,
// 102-reg cap >> ~85-reg live set. Compute codegen = R8's unroll-2 carry-
// paired conflict-free float2 tile stores, duplicated for the second pair.

#define TPB 128
#define EDGES_PER_BLOCK 512   // TPB * 4
#define TILE_BYTES 38912      // 512 * 19 * 4
#define HALF_ROWS (EDGES_PER_BLOCK / 2 * 19)   // float offset of pair-B half

typedef unsigned long long u64;

__device__ int g_batch_is64;   // 1 if batch is int64, 0 if int32

struct CWPack {
    u64 w1p[40];    // {W1[c][k]}x2, index c*10+k
    u64 b1p[10];    // {b1[k]}x2
    u64 w2p[190];   // {W2[k][j]}x2 transposed, index j*10+k  (16B-aligned rows)
    u64 b2p[19];    // {b2[j]}x2
    u64 pad;
};

__device__ CWPack g_wscratch;      // staging (written by prep kernel)
__constant__ CWPack c_w;           // read-only broadcast copy

__device__ __forceinline__ u64 pack2(float lo, float hi) {
    u64 r;
    asm("mov.b64 %0, {%1, %2};" : "=l"(r) : "f"(lo), "f"(hi));
    return r;
}

__device__ __forceinline__ void unpack2(u64 v, float& lo, float& hi) {
    asm("mov.b64 {%0, %1}, %2;" : "=f"(lo), "=f"(hi) : "l"(v));
}

__device__ __forceinline__ u64 fma2(u64 a, u64 b, u64 c) {
    u64 d;
    asm("fma.rn.f32x2 %0, %1, %2, %3;" : "=l"(d) : "l"(a), "l"(b), "l"(c));
    return d;
}

__device__ __forceinline__ u64 relu2(u64 v) {
    float lo, hi;
    unpack2(v, lo, hi);
    lo = fmaxf(lo, 0.0f);
    hi = fmaxf(hi, 0.0f);
    return pack2(lo, hi);
}

// Build weight pack + detect batch dtype (int64 values 0..4095 -> all odd
// int32 words zero; 1024 random int32 in [0,4096) all-zero: impossible).
__global__ void prep_weights(const float* __restrict__ W1,
                             const float* __restrict__ b1,
                             const float* __restrict__ W2,
                             const float* __restrict__ b2,
                             const int*   __restrict__ b32)
{
    int t = threadIdx.x;
    if (t < 40)             g_wscratch.w1p[t]      = pack2(W1[t], W1[t]);
    if (t >= 64 && t < 74)  g_wscratch.b1p[t - 64] = pack2(b1[t - 64], b1[t - 64]);
    if (t >= 96 && t < 115) g_wscratch.b2p[t - 96] = pack2(b2[t - 96], b2[t - 96]);
    if (t < 190) {
        int j = t / 10, k = t - j * 10;   // transpose
        float w = W2[k * 19 + j];
        g_wscratch.w2p[t] = pack2(w, w);
    }
    if (t == 255) g_wscratch.pad = 0;

    if (t >= 192 && t < 224) {            // warp 6: parallel dtype scan
        int lane = t - 192;
        int bad = 0;
        #pragma unroll 4
        for (int i = 0; i < 32; i++)
            bad |= b32[1 + 2 * (lane * 32 + i)];
        unsigned any = __ballot_sync(0xffffffffu, bad != 0);
        if (lane == 0) g_batch_is64 = (any == 0) ? 1 : 0;
    }
}

__global__ __launch_bounds__(TPB, 5)
void edge_model_kernel(const float* __restrict__ src,
                       const float* __restrict__ dest,
                       const float* __restrict__ ea,
                       const float* __restrict__ u,
                       const void*  __restrict__ batch_raw,
                       float* __restrict__ out,        // [E,19]
                       long long E)
{
    __shared__ __align__(16) float otile[EDGES_PER_BLOCK * 19];  // 38912 B

    const int t = threadIdx.x;
    const int is64 = g_batch_is64;

    const long long base = (long long)blockIdx.x * EDGES_PER_BLOCK;

    if (base + EDGES_PER_BLOCK <= E) {
        // ========= fast path: 512-edge block, 4 edges/thread (2 packed pairs) =========
        const long long P = base >> 1;          // first pair of block
        const long long p0 = P + t;             // pair A -> edges 2t, 2t+1
        const long long p1 = P + TPB + t;       // pair B -> edges 256+2t, 256+2t+1

        // Batch indices first (head the dependent batch -> u chain).
        long long i00, i01, i10, i11;
        if (is64) {
            longlong2 q0 = ((const longlong2*)batch_raw)[p0];
            longlong2 q1 = ((const longlong2*)batch_raw)[p1];
            i00 = q0.x; i01 = q0.y; i10 = q1.x; i11 = q1.y;
        } else {
            int2 q0 = ((const int2*)batch_raw)[p0];
            int2 q1 = ((const int2*)batch_raw)[p1];
            i00 = q0.x; i01 = q0.y; i10 = q1.x; i11 = q1.y;
        }
        const u64 up0 = pack2(__ldg(&u[i00]), __ldg(&u[i01]));
        const u64 up1 = pack2(__ldg(&u[i10]), __ldg(&u[i11]));

        const float2 s0 = ((const float2*)src)[p0];
        const float2 d0 = ((const float2*)dest)[p0];
        const float2 a0 = ((const float2*)ea)[p0];
        const float2 s1 = ((const float2*)src)[p1];
        const float2 d1 = ((const float2*)dest)[p1];
        const float2 a1 = ((const float2*)ea)[p1];

        const u64 sp0 = pack2(s0.x, s0.y), sp1 = pack2(s1.x, s1.y);
        const u64 dp0 = pack2(d0.x, d0.y), dp1 = pack2(d1.x, d1.y);
        const u64 ap0 = pack2(a0.x, a0.y), ap1 = pack2(a1.x, a1.y);

        // layer 1 for both pairs — every LDC serves 4 edges.
        u64 h0[10], h1[10];
        #pragma unroll
        for (int k = 0; k < 10; k++) {
            const u64 wa = c_w.w1p[k],      wb = c_w.w1p[10 + k];
            const u64 wc = c_w.w1p[20 + k], wd = c_w.w1p[30 + k];
            const u64 bb = c_w.b1p[k];
            u64 acc0 = bb, acc1 = bb;
            acc0 = fma2(sp0, wa, acc0);  acc1 = fma2(sp1, wa, acc1);
            acc0 = fma2(dp0, wb, acc0);  acc1 = fma2(dp1, wb, acc1);
            acc0 = fma2(ap0, wc, acc0);  acc1 = fma2(ap1, wc, acc1);
            acc0 = fma2(up0, wd, acc0);  acc1 = fma2(up1, wd, acc1);
            h0[k] = relu2(acc0);
            h1[k] = relu2(acc1);
        }

        // layer 2: R8 carry-paired conflict-free float2 stores, two pairs.
        // Pair A rows at words 38t / 38t+19; pair B rows offset by HALF_ROWS.
        // All float2 stores land at even word offsets; u64 lane stride 19
        // (odd) -> conflict-free.
        float* r0a = &otile[(2 * t)     * 19];
        float* r0b = &otile[(2 * t + 1) * 19];
        float* r1a = &otile[HALF_ROWS + (2 * t)     * 19];
        float* r1b = &otile[HALF_ROWS + (2 * t + 1) * 19];

        u64 prev0, prev1;
        {   // j = 0
            u64 acc0 = c_w.b2p[0], acc1 = acc0;
            const ulonglong2* wr = (const ulonglong2*)&c_w.w2p[0];
            #pragma unroll
            for (int kk = 0; kk < 5; kk++) {
                ulonglong2 w = wr[kk];
                acc0 = fma2(h0[2 * kk],     w.x, acc0);
                acc0 = fma2(h0[2 * kk + 1], w.y, acc0);
                acc1 = fma2(h1[2 * kk],     w.x, acc1);
                acc1 = fma2(h1[2 * kk + 1], w.y, acc1);
            }
            float lo, hi;
            unpack2(acc0, lo, hi);  r0b[0] = hi;
            unpack2(acc1, lo, hi);  r1b[0] = hi;
            prev0 = acc0;  prev1 = acc1;
        }
        #pragma unroll 2
        for (int j = 1; j < 19; j++) {
            u64 acc0 = c_w.b2p[j], acc1 = acc0;
            const ulonglong2* wr = (const ulonglong2*)&c_w.w2p[j * 10];  // 16B aligned
            #pragma unroll
            for (int kk = 0; kk < 5; kk++) {
                ulonglong2 w = wr[kk];
                acc0 = fma2(h0[2 * kk],     w.x, acc0);
                acc0 = fma2(h0[2 * kk + 1], w.y, acc0);
                acc1 = fma2(h1[2 * kk],     w.x, acc1);
                acc1 = fma2(h1[2 * kk + 1], w.y, acc1);
            }
            float pl, ph, cl, ch;
            unpack2(prev0, pl, ph);
            unpack2(acc0,  cl, ch);
            if (j & 1) *(float2*)(r0a + j - 1) = make_float2(pl, cl);
            else       *(float2*)(r0b + j - 1) = make_float2(ph, ch);
            unpack2(prev1, pl, ph);
            unpack2(acc1,  cl, ch);
            if (j & 1) *(float2*)(r1a + j - 1) = make_float2(pl, cl);
            else       *(float2*)(r1b + j - 1) = make_float2(ph, ch);
            prev0 = acc0;  prev1 = acc1;
        }
        {   // tails: r0a[18], r1a[18]
            float lo, hi;
            unpack2(prev0, lo, hi);  r0a[18] = lo;
            unpack2(prev1, lo, hi);  r1a[18] = lo;
        }
        __syncthreads();

        // One TMA bulk store flushes the whole tile.
        if (t == 0) {
            unsigned saddr = (unsigned)__cvta_generic_to_shared(otile);
            const float* g = out + base * 19;   // 16B-aligned
            asm volatile("fence.proxy.async.shared::cta;" ::: "memory");
            asm volatile(
                "cp.async.bulk.global.shared::cta.bulk_group [%0], [%1], %2;"
                :: "l"(g), "r"(saddr), "r"((unsigned)TILE_BYTES) : "memory");
            asm volatile("cp.async.bulk.commit_group;" ::: "memory");
            asm volatile("cp.async.bulk.wait_group 0;" ::: "memory");
        }
    } else {
        // ================= tail path (scalar, bounds-checked) =================
        for (long long e = base + t; e < E; e += TPB) {
            float x0 = src[e], x1 = dest[e], x2 = ea[e];
            long long bi = is64 ? ((const long long*)batch_raw)[e]
                                : (long long)((const int*)batch_raw)[e];
            float x3 = u[bi];
            float h[10];
            #pragma unroll
            for (int k = 0; k < 10; k++) {
                float lo, hiu;
                unpack2(c_w.w1p[k], lo, hiu);       float wa = lo;
                unpack2(c_w.w1p[10 + k], lo, hiu);  float wb = lo;
                unpack2(c_w.w1p[20 + k], lo, hiu);  float wc = lo;
                unpack2(c_w.w1p[30 + k], lo, hiu);  float wd = lo;
                unpack2(c_w.b1p[k], lo, hiu);
                float acc = lo;
                acc = fmaf(x0, wa, acc);
                acc = fmaf(x1, wb, acc);
                acc = fmaf(x2, wc, acc);
                acc = fmaf(x3, wd, acc);
                h[k] = fmaxf(acc, 0.0f);
            }
            #pragma unroll
            for (int j = 0; j < 19; j++) {
                float lo, hiu;
                unpack2(c_w.b2p[j], lo, hiu);
                float acc = lo;
                #pragma unroll
                for (int k = 0; k < 10; k++) {
                    unpack2(c_w.w2p[j * 10 + k], lo, hiu);
                    acc = fmaf(h[k], lo, acc);
                }
                out[e * 19 + j] = acc;
            }
        }
    }
}

extern "C" void kernel_launch(void* const* d_in, const int* in_sizes, int n_in,
                              void* d_out, int out_size)
{
    const float* src   = (const float*)d_in[0];
    const float* dest  = (const float*)d_in[1];
    const float* ea    = (const float*)d_in[2];
    const float* u     = (const float*)d_in[3];
    const void*  batch = d_in[4];
    const float* W1    = (const float*)d_in[5];
    const float* b1    = (const float*)d_in[6];
    const float* W2    = (const float*)d_in[7];
    const float* b2    = (const float*)d_in[8];
    float* out = (float*)d_out;

    const long long E = in_sizes[0];
    const int blocks = (int)((E + EDGES_PER_BLOCK - 1) / EDGES_PER_BLOCK);

    prep_weights<<<1, 256>>>(W1, b1, W2, b2, (const int*)batch);

    void* scratch_addr = nullptr;
    cudaGetSymbolAddress(&scratch_addr, g_wscratch);
    cudaMemcpyToSymbolAsync(c_w, scratch_addr, sizeof(CWPack), 0,
                            cudaMemcpyDeviceToDevice, 0);

    edge_model_kernel<<<blocks, TPB>>>(src, dest, ea, u, batch, out, E);
}